// round 10
// baseline (speedup 1.0000x reference)
#include <cuda_runtime.h>
#include <cstdint>

// -------------------- problem constants --------------------
#define B_SZ 4096
#define I_SZ 1024
#define H_SZ 2048
#define NSTEPS 5
#define DT_C 0.1f

// -------------------- GEMM tiling (exact R4) --------------------
#define BM 128
#define BN 256
#define BK 16
#define NSTAGE 4
#define THREADS 256

#define SA_BYTES (BM * BK * 4)                 // 8192
#define SB_BYTES (BN * BK * 4)                 // 16384
#define STAGE_BYTES (SA_BYTES + SB_BYTES)      // 24576
#define SMEM_TOTAL (NSTAGE * STAGE_BYTES)      // 98304

// -------------------- scratch --------------------
__device__ float g_C1[B_SZ * H_SZ];
__device__ float g_C2[B_SZ * H_SZ];
__device__ float g_G1[B_SZ * H_SZ];
__device__ float g_hA[B_SZ * H_SZ];
__device__ float g_hB[B_SZ * H_SZ];
__device__ int   g_flags[2048];          // [step][mblk][nblk] ready flags

// -------------------- PTX helpers --------------------
__device__ __forceinline__ void cp16(uint32_t smem, const void* g) {
    asm volatile("cp.async.cg.shared.global [%0], [%1], 16;" :: "r"(smem), "l"(g) : "memory");
}
__device__ __forceinline__ void cp_commit() {
    asm volatile("cp.async.commit_group;" ::: "memory");
}
template <int N>
__device__ __forceinline__ void cp_wait() {
    asm volatile("cp.async.wait_group %0;" :: "n"(N) : "memory");
}
__device__ __forceinline__ void ldsm4(uint32_t* r, uint32_t a) {
    asm volatile("ldmatrix.sync.aligned.m8n8.x4.shared.b16 {%0,%1,%2,%3}, [%4];"
                 : "=r"(r[0]), "=r"(r[1]), "=r"(r[2]), "=r"(r[3]) : "r"(a));
}
__device__ __forceinline__ void mma_tf32(float* d, const uint32_t* a, const uint32_t* b) {
    asm volatile(
        "mma.sync.aligned.m16n8k8.row.col.f32.tf32.tf32.f32 "
        "{%0,%1,%2,%3}, {%4,%5,%6,%7}, {%8,%9}, {%0,%1,%2,%3};"
        : "+f"(d[0]), "+f"(d[1]), "+f"(d[2]), "+f"(d[3])
        : "r"(a[0]), "r"(a[1]), "r"(a[2]), "r"(a[3]), "r"(b[0]), "r"(b[1]));
}
__device__ __forceinline__ uint32_t swadr(uint32_t base, int r, int g) {
    const int c = g ^ (r & 3) ^ ((r >> 2) & 1);
    return base + (uint32_t)(r * 64 + c * 16);
}

// -------------------- flags reset --------------------
__global__ void reset_flags_kernel() {
    for (int i = threadIdx.x; i < 2048; i += 256) g_flags[i] = 0;
}

// -------------------- dual-B tf32 GEMM (R4 body) --------------------
// grid (16, 32): half = blockIdx.x>>3 selects B0->C0 or B1->C1 path.
// LIQ=0: C_half = A @ B_half^T + bias_half  (invariant launch)
// LIQ=1: half0 computes G1 = A@B0^T, writes it + release flag.
//        half1 computes G2 = A@B1^T, acquires partner's G1 tile, applies
//        liquid update: C1(out h), o_tau; eC1,eC2,eh,etb inputs.
template <int LIQ>
__global__ void __launch_bounds__(THREADS, 1)
gemm_dual_tf32(const float* __restrict__ A, int lda,
               const float* __restrict__ B0, int ldb0, float* __restrict__ C0,
               const float* __restrict__ bias0,
               const float* __restrict__ B1, int ldb1, float* __restrict__ C1,
               const float* __restrict__ bias1,
               int K,
               const float* __restrict__ eC1, const float* __restrict__ eC2,
               const float* __restrict__ eh,  const float* __restrict__ etb,
               float* __restrict__ o_tau, int step)
{
    extern __shared__ __align__(1024) char smem[];
    const uint32_t sb = (uint32_t)__cvta_generic_to_shared(smem);

    const int tid  = threadIdx.x;
    const int lane = tid & 31;
    const int wid  = tid >> 5;
    const int wm   = (wid >> 2) * 64;
    const int wn   = (wid & 3) * 64;

    const int half = blockIdx.x >> 3;
    const int nblk = blockIdx.x & 7;
    const int m0 = blockIdx.y * BM;
    const int n0 = nblk * BN;

    const float* Bw   = half ? B1 : B0;
    const int    ldb  = half ? ldb1 : ldb0;
    float*       C    = half ? C1 : C0;
    const float* bias = half ? bias1 : bias0;

    const int lr = tid >> 2;
    const int lg = tid & 3;
    const float* gA = A  + (long)(m0 + lr) * lda + lg * 4;
    const float* gB = Bw + (long)(n0 + lr) * ldb + lg * 4;
    const long strideA64 = (long)64 * lda;
    const long strideB64 = (long)64 * ldb;

    const int arow = (lane & 7) + ((lane >> 3) & 1) * 8;
    const int agof = (lane >> 4);
    const int brow = (lane & 7) + ((lane >> 4) & 1) * 8;
    const int bgof = (lane >> 3) & 1;

    float acc[4][8][4];
#pragma unroll
    for (int mt = 0; mt < 4; mt++)
#pragma unroll
        for (int nt = 0; nt < 8; nt++)
#pragma unroll
            for (int r = 0; r < 4; r++) acc[mt][nt][r] = 0.f;

    const int nK = K / BK;

    auto load_stage = [&](int s, int kt) {
        const uint32_t sA = sb + s * STAGE_BYTES;
        const uint32_t sB = sA + SA_BYTES;
        const int koff = kt * BK;
        cp16(swadr(sA, lr,       lg), gA + koff);
        cp16(swadr(sA, lr + 64,  lg), gA + koff + strideA64);
        cp16(swadr(sB, lr,       lg), gB + koff);
        cp16(swadr(sB, lr + 64,  lg), gB + koff + strideB64);
        cp16(swadr(sB, lr + 128, lg), gB + koff + 2 * strideB64);
        cp16(swadr(sB, lr + 192, lg), gB + koff + 3 * strideB64);
    };

#pragma unroll
    for (int s = 0; s < NSTAGE - 1; s++) {
        load_stage(s, s);
        cp_commit();
    }

    for (int kt = 0; kt < nK; kt++) {
        cp_wait<NSTAGE - 2>();
        __syncthreads();

        const int kload = kt + NSTAGE - 1;
        if (kload < nK) load_stage(kload & (NSTAGE - 1), kload);
        cp_commit();

        const uint32_t sA = sb + (kt & (NSTAGE - 1)) * STAGE_BYTES;
        const uint32_t sB = sA + SA_BYTES;

#pragma unroll
        for (int ks = 0; ks < 2; ks++) {
            uint32_t af[4][4], bf[4][4];
#pragma unroll
            for (int mt = 0; mt < 4; mt++)
                ldsm4(af[mt], swadr(sA, wm + mt * 16 + arow, 2 * ks + agof));
#pragma unroll
            for (int p = 0; p < 4; p++)
                ldsm4(bf[p], swadr(sB, wn + p * 16 + brow, 2 * ks + bgof));
#pragma unroll
            for (int mt = 0; mt < 4; mt++)
#pragma unroll
                for (int p = 0; p < 4; p++) {
                    mma_tf32(acc[mt][2 * p],     af[mt], &bf[p][0]);
                    mma_tf32(acc[mt][2 * p + 1], af[mt], &bf[p][2]);
                }
        }
    }

    // ---- epilogue ----
    const int grp = lane >> 2;
    const int tig = lane & 3;

    if (LIQ == 0 || half == 0) {
        // plain store (+bias for LIQ=0)
#pragma unroll
        for (int mt = 0; mt < 4; mt++) {
            const int row0 = m0 + wm + mt * 16 + grp;
#pragma unroll
            for (int nt = 0; nt < 8; nt++) {
                const int col = n0 + wn + nt * 8 + 2 * tig;
                float b0 = 0.f, b1 = 0.f;
                if (LIQ == 0 && bias) { b0 = __ldg(bias + col); b1 = __ldg(bias + col + 1); }
                float2 v0, v1;
                v0.x = acc[mt][nt][0] + b0; v0.y = acc[mt][nt][1] + b1;
                v1.x = acc[mt][nt][2] + b0; v1.y = acc[mt][nt][3] + b1;
                *(float2*)(C + (long)row0 * H_SZ + col)       = v0;
                *(float2*)(C + (long)(row0 + 8) * H_SZ + col) = v1;
            }
        }
        if (LIQ == 1) {
            // publish G1 tile
            __syncthreads();
            if (tid == 0) {
                __threadfence();
                g_flags[step * 256 + blockIdx.y * 8 + nblk] = 1;
            }
        }
    } else {
        // half == 1, LIQ == 1: wait for partner's G1 tile, fuse liquid step
        volatile int* flag = (volatile int*)&g_flags[step * 256 + blockIdx.y * 8 + nblk];
        if (tid == 0) {
            while (*flag == 0) { __nanosleep(64); }
        }
        __syncthreads();
        __threadfence();   // acquire: order subsequent G1 loads after flag observation

        const float* G1 = C0;
#pragma unroll
        for (int mt = 0; mt < 4; mt++) {
            const int row0 = m0 + wm + mt * 16 + grp;
#pragma unroll
            for (int nt = 0; nt < 8; nt++) {
                const int col = n0 + wn + nt * 8 + 2 * tig;
                const float2 tb = *(const float2*)(etb + col);
#pragma unroll
                for (int rr = 0; rr < 2; rr++) {
                    const long off = (long)(row0 + rr * 8) * H_SZ + col;
                    const float2 g1v = *(const float2*)(G1 + off);
                    const float2 c1v = *(const float2*)(eC1 + off);
                    const float2 c2v = *(const float2*)(eC2 + off);
                    const float2 hv  = *(const float2*)(eh  + off);
                    float2 hn, tv;
                    {
                        const float g2  = acc[mt][nt][2 * rr];
                        const float tl  = c2v.x + g1v.x;
                        const float sg  = 1.f / (1.f + expf(-tl));
                        const float tau = tb.x * (0.5f + sg);
                        const float act = tanhf(g2 + c1v.x);
                        hn.x = hv.x + DT_C * (act - hv.x) / tau;
                        tv.x = tau;
                    }
                    {
                        const float g2  = acc[mt][nt][2 * rr + 1];
                        const float tl  = c2v.y + g1v.y;
                        const float sg  = 1.f / (1.f + expf(-tl));
                        const float tau = tb.y * (0.5f + sg);
                        const float act = tanhf(g2 + c1v.y);
                        hn.y = hv.y + DT_C * (act - hv.y) / tau;
                        tv.y = tau;
                    }
                    *(float2*)(C1 + off) = hn;          // h_out
                    if (o_tau) *(float2*)(o_tau + off) = tv;
                }
            }
        }
    }
}

// -------------------- launcher --------------------
extern "C" void kernel_launch(void* const* d_in, const int* in_sizes, int n_in,
                              void* d_out, int out_size)
{
    (void)in_sizes; (void)n_in; (void)out_size;

    const float* x           = (const float*)d_in[0];
    const float* hidden      = (const float*)d_in[1];
    const float* W_rec       = (const float*)d_in[2];
    const float* W_in_w      = (const float*)d_in[3];
    const float* W_in_b      = (const float*)d_in[4];
    const float* tau_base    = (const float*)d_in[5];
    const float* tau_adapt_w = (const float*)d_in[6];
    const float* tau_adapt_b = (const float*)d_in[7];

    float* out_h   = (float*)d_out;
    float* out_tau = out_h + (long)B_SZ * H_SZ;

    float *C1, *C2, *G1, *hA, *hB;
    cudaGetSymbolAddress((void**)&C1, g_C1);
    cudaGetSymbolAddress((void**)&C2, g_C2);
    cudaGetSymbolAddress((void**)&G1, g_G1);
    cudaGetSymbolAddress((void**)&hA, g_hA);
    cudaGetSymbolAddress((void**)&hB, g_hB);

    cudaFuncSetAttribute(gemm_dual_tf32<0>, cudaFuncAttributeMaxDynamicSharedMemorySize, SMEM_TOTAL);
    cudaFuncSetAttribute(gemm_dual_tf32<1>, cudaFuncAttributeMaxDynamicSharedMemorySize, SMEM_TOTAL);

    const int ldtau = I_SZ + H_SZ;     // 3072
    dim3 gg(16, B_SZ / BM);            // (16, 32) = 512 CTAs

    reset_flags_kernel<<<1, 256>>>();

    // invariants: C1 = x@W_in^T + W_in_b ; C2 = x@tau_x^T + tau_adapt_b
    gemm_dual_tf32<0><<<gg, THREADS, SMEM_TOTAL>>>(
        x, I_SZ,
        W_in_w, I_SZ, C1, W_in_b,
        tau_adapt_w, ldtau, C2, tau_adapt_b,
        I_SZ,
        nullptr, nullptr, nullptr, nullptr, nullptr, 0);

    // 5 fused steps: half0 -> G1 = h@tau_h^T (+flag), half1 -> G2 = h@W_rec^T + liquid
    const float* h = hidden;
    float* bufs[2] = {hA, hB};
    for (int s = 0; s < NSTEPS; s++) {
        float* ho = (s == NSTEPS - 1) ? out_h   : bufs[s & 1];
        float* to = (s == NSTEPS - 1) ? out_tau : nullptr;
        gemm_dual_tf32<1><<<gg, THREADS, SMEM_TOTAL>>>(
            h, H_SZ,
            tau_adapt_w + I_SZ, ldtau, G1, nullptr,
            W_rec, H_SZ, ho, nullptr,
            H_SZ,
            C1, C2, h, tau_base, to, s);
        h = ho;
    }
}

// round 11
// speedup vs baseline: 1.9926x; 1.9926x over previous
#include <cuda_runtime.h>
#include <cuda_fp16.h>
#include <cstdint>

// -------------------- problem constants --------------------
#define B_SZ 4096
#define I_SZ 1024
#define H_SZ 2048
#define NSTEPS 5
#define DT_C 0.1f

// -------------------- GEMM tiling (R4 structure, fp16 data) ---------------
#define BM 128
#define BN 256
#define BK 32                 // 32 halves per k-tile = 64B rows (same layout)
#define NSTAGE 4
#define THREADS 256

#define SA_BYTES (BM * 64)                    // 8192
#define SB_BYTES (BN * 64)                    // 16384
#define STAGE_BYTES (SA_BYTES + SB_BYTES)     // 24576
#define SMEM_TOTAL (NSTAGE * STAGE_BYTES)     // 98304

// -------------------- scratch --------------------
__device__ float  g_C1[B_SZ * H_SZ];
__device__ float  g_C2[B_SZ * H_SZ];
__device__ float  g_G1[B_SZ * H_SZ];
__device__ float  g_G2[B_SZ * H_SZ];
__device__ float  g_h [B_SZ * H_SZ];
__device__ __half g_h16  [B_SZ * H_SZ];
__device__ __half g_x16  [B_SZ * I_SZ];
__device__ __half g_Wrec16[H_SZ * H_SZ];
__device__ __half g_tauh16[H_SZ * H_SZ];
__device__ __half g_Win16 [H_SZ * I_SZ];
__device__ __half g_taux16[H_SZ * I_SZ];

// -------------------- PTX helpers --------------------
__device__ __forceinline__ void cp16(uint32_t smem, const void* g) {
    asm volatile("cp.async.cg.shared.global [%0], [%1], 16;" :: "r"(smem), "l"(g) : "memory");
}
__device__ __forceinline__ void cp_commit() {
    asm volatile("cp.async.commit_group;" ::: "memory");
}
template <int N>
__device__ __forceinline__ void cp_wait() {
    asm volatile("cp.async.wait_group %0;" :: "n"(N) : "memory");
}
__device__ __forceinline__ void ldsm4(uint32_t* r, uint32_t a) {
    asm volatile("ldmatrix.sync.aligned.m8n8.x4.shared.b16 {%0,%1,%2,%3}, [%4];"
                 : "=r"(r[0]), "=r"(r[1]), "=r"(r[2]), "=r"(r[3]) : "r"(a));
}
__device__ __forceinline__ void mma_f16(float* d, const uint32_t* a, const uint32_t* b) {
    asm volatile(
        "mma.sync.aligned.m16n8k16.row.col.f32.f16.f16.f32 "
        "{%0,%1,%2,%3}, {%4,%5,%6,%7}, {%8,%9}, {%0,%1,%2,%3};"
        : "+f"(d[0]), "+f"(d[1]), "+f"(d[2]), "+f"(d[3])
        : "r"(a[0]), "r"(a[1]), "r"(a[2]), "r"(a[3]), "r"(b[0]), "r"(b[1]));
}
// swizzled smem byte address for 16B chunk (row r of 64B, chunk g of 4)
__device__ __forceinline__ uint32_t swadr(uint32_t base, int r, int g) {
    const int c = g ^ (r & 3) ^ ((r >> 2) & 1);
    return base + (uint32_t)(r * 64 + c * 16);
}

// -------------------- fp32 -> fp16 convert (strided, 8 elts/thread) -------
__global__ void cvt16_kernel(const float* __restrict__ src, int srld,
                             __half* __restrict__ dst, int dsld,
                             int rows, int cols)
{
    const int per_row = cols >> 3;
    const long total = (long)rows * per_row;
    for (long i = (long)blockIdx.x * blockDim.x + threadIdx.x; i < total;
         i += (long)gridDim.x * blockDim.x) {
        const int r = (int)(i / per_row);
        const int c = (int)(i % per_row) << 3;
        const float4 a = *(const float4*)(src + (long)r * srld + c);
        const float4 b = *(const float4*)(src + (long)r * srld + c + 4);
        __half2 h0 = __float22half2_rn(make_float2(a.x, a.y));
        __half2 h1 = __float22half2_rn(make_float2(a.z, a.w));
        __half2 h2 = __float22half2_rn(make_float2(b.x, b.y));
        __half2 h3 = __float22half2_rn(make_float2(b.z, b.w));
        uint4 u;
        u.x = *(uint32_t*)&h0; u.y = *(uint32_t*)&h1;
        u.z = *(uint32_t*)&h2; u.w = *(uint32_t*)&h3;
        *(uint4*)(dst + (long)r * dsld + c) = u;
    }
}

// -------------------- dual-B fp16 GEMM (R4 body, half data) ---------------
// C_half[M, H_SZ]: tile = A[m0:+128, :K] @ Bh[n0:+256, :K]^T (+bias_h)
__global__ void __launch_bounds__(THREADS, 1)
gemm_dual_f16(const __half* __restrict__ A, int lda,
              const __half* __restrict__ B0, int ldb0, float* __restrict__ C0,
              const float* __restrict__ bias0,
              const __half* __restrict__ B1, int ldb1, float* __restrict__ C1,
              const float* __restrict__ bias1,
              int K)
{
    extern __shared__ __align__(1024) char smem[];
    const uint32_t sb = (uint32_t)__cvta_generic_to_shared(smem);

    const int tid  = threadIdx.x;
    const int lane = tid & 31;
    const int wid  = tid >> 5;
    const int wm   = (wid >> 2) * 64;
    const int wn   = (wid & 3) * 64;

    const int half_ = blockIdx.x >> 3;
    const int nblk  = blockIdx.x & 7;
    const int m0 = blockIdx.y * BM;
    const int n0 = nblk * BN;

    const __half* Bw   = half_ ? B1 : B0;
    const int     ldb  = half_ ? ldb1 : ldb0;
    float*        C    = half_ ? C1 : C0;
    const float*  bias = half_ ? bias1 : bias0;

    // ---- loader coordinates: row lr (0..63), 16B chunk lg (8 halves) ----
    const int lr = tid >> 2;
    const int lg = tid & 3;
    const __half* gA = A  + (long)(m0 + lr) * lda + lg * 8;
    const __half* gB = Bw + (long)(n0 + lr) * ldb + lg * 8;
    const long strideA64 = (long)64 * lda;
    const long strideB64 = (long)64 * ldb;

    // ---- ldmatrix lane coordinates (16x16 b16 tiles) ----
    const int arow = (lane & 7) + ((lane >> 3) & 1) * 8;
    const int agof = (lane >> 4);
    const int brow = (lane & 7) + ((lane >> 4) & 1) * 8;
    const int bgof = (lane >> 3) & 1;

    float acc[4][8][4];
#pragma unroll
    for (int mt = 0; mt < 4; mt++)
#pragma unroll
        for (int nt = 0; nt < 8; nt++)
#pragma unroll
            for (int r = 0; r < 4; r++) acc[mt][nt][r] = 0.f;

    const int nK = K / BK;

    // ---- stage loader (6 cp.async per thread) ----
    auto load_stage = [&](int s, int kt) {
        const uint32_t sA = sb + s * STAGE_BYTES;
        const uint32_t sB = sA + SA_BYTES;
        const int koff = kt * BK;
        cp16(swadr(sA, lr,       lg), gA + koff);
        cp16(swadr(sA, lr + 64,  lg), gA + koff + strideA64);
        cp16(swadr(sB, lr,       lg), gB + koff);
        cp16(swadr(sB, lr + 64,  lg), gB + koff + strideB64);
        cp16(swadr(sB, lr + 128, lg), gB + koff + 2 * strideB64);
        cp16(swadr(sB, lr + 192, lg), gB + koff + 3 * strideB64);
    };

#pragma unroll
    for (int s = 0; s < NSTAGE - 1; s++) {
        load_stage(s, s);
        cp_commit();
    }

    for (int kt = 0; kt < nK; kt++) {
        cp_wait<NSTAGE - 2>();
        __syncthreads();

        const int kload = kt + NSTAGE - 1;
        if (kload < nK) load_stage(kload & (NSTAGE - 1), kload);
        cp_commit();

        const uint32_t sA = sb + (kt & (NSTAGE - 1)) * STAGE_BYTES;
        const uint32_t sB = sA + SA_BYTES;

        // two k=16 groups per 64B row (chunks {0,1} then {2,3})
#pragma unroll
        for (int ks = 0; ks < 2; ks++) {
            uint32_t af[4][4], bf[4][4];
#pragma unroll
            for (int mt = 0; mt < 4; mt++)
                ldsm4(af[mt], swadr(sA, wm + mt * 16 + arow, 2 * ks + agof));
#pragma unroll
            for (int p = 0; p < 4; p++)
                ldsm4(bf[p], swadr(sB, wn + p * 16 + brow, 2 * ks + bgof));
#pragma unroll
            for (int mt = 0; mt < 4; mt++)
#pragma unroll
                for (int p = 0; p < 4; p++) {
                    mma_f16(acc[mt][2 * p],     af[mt], &bf[p][0]);
                    mma_f16(acc[mt][2 * p + 1], af[mt], &bf[p][2]);
                }
        }
    }

    // ---- epilogue ----
    const int grp = lane >> 2;
    const int tig = lane & 3;
#pragma unroll
    for (int mt = 0; mt < 4; mt++) {
        const int row0 = m0 + wm + mt * 16 + grp;
#pragma unroll
        for (int nt = 0; nt < 8; nt++) {
            const int col = n0 + wn + nt * 8 + 2 * tig;
            float b0 = 0.f, b1 = 0.f;
            if (bias) { b0 = __ldg(bias + col); b1 = __ldg(bias + col + 1); }
            float2 v0, v1;
            v0.x = acc[mt][nt][0] + b0; v0.y = acc[mt][nt][1] + b1;
            v1.x = acc[mt][nt][2] + b0; v1.y = acc[mt][nt][3] + b1;
            *(float2*)(C + (long)row0 * H_SZ + col)       = v0;
            *(float2*)(C + (long)(row0 + 8) * H_SZ + col) = v1;
        }
    }
}

// -------------------- elementwise liquid step (+fp16 h out) ---------------
__global__ void __launch_bounds__(256)
liquid_step_kernel(const float* __restrict__ h_in,
                   const float* __restrict__ G1,
                   const float* __restrict__ G2,
                   const float* __restrict__ C1,
                   const float* __restrict__ C2,
                   const float* __restrict__ tau_base,
                   float* __restrict__ h_out,
                   __half* __restrict__ h16_out,
                   float* __restrict__ tau_out)
{
    const int idx = (blockIdx.x * 256 + threadIdx.x) * 4;
    const int j = idx & (H_SZ - 1);

    float4 g1 = *(const float4*)(G1 + idx);
    float4 g2 = *(const float4*)(G2 + idx);
    float4 c1 = *(const float4*)(C1 + idx);
    float4 c2 = *(const float4*)(C2 + idx);
    float4 hv = *(const float4*)(h_in + idx);
    float4 tb = *(const float4*)(tau_base + j);

    float4 hn, tv;
#define ONE_LANE(f)                                                        \
    {                                                                      \
        float tl  = c2.f + g1.f;                                           \
        float sg  = 1.f / (1.f + expf(-tl));                               \
        float tau = tb.f * (0.5f + sg);                                    \
        float act = tanhf(g2.f + c1.f);                                    \
        hn.f = hv.f + DT_C * (act - hv.f) / tau;                           \
        tv.f = tau;                                                        \
    }
    ONE_LANE(x) ONE_LANE(y) ONE_LANE(z) ONE_LANE(w)
#undef ONE_LANE

    *(float4*)(h_out + idx) = hn;
    __half2 p0 = __float22half2_rn(make_float2(hn.x, hn.y));
    __half2 p1 = __float22half2_rn(make_float2(hn.z, hn.w));
    uint2 u; u.x = *(uint32_t*)&p0; u.y = *(uint32_t*)&p1;
    *(uint2*)(h16_out + idx) = u;
    if (tau_out) *(float4*)(tau_out + idx) = tv;
}

// -------------------- launcher --------------------
extern "C" void kernel_launch(void* const* d_in, const int* in_sizes, int n_in,
                              void* d_out, int out_size)
{
    (void)in_sizes; (void)n_in; (void)out_size;

    const float* x           = (const float*)d_in[0];
    const float* hidden      = (const float*)d_in[1];
    const float* W_rec       = (const float*)d_in[2];
    const float* W_in_w      = (const float*)d_in[3];
    const float* W_in_b      = (const float*)d_in[4];
    const float* tau_base    = (const float*)d_in[5];
    const float* tau_adapt_w = (const float*)d_in[6];
    const float* tau_adapt_b = (const float*)d_in[7];

    float* out_h   = (float*)d_out;
    float* out_tau = out_h + (long)B_SZ * H_SZ;

    float *C1, *C2, *G1, *G2, *hbuf;
    __half *x16, *h16, *Wrec16, *tauh16, *Win16, *taux16;
    cudaGetSymbolAddress((void**)&C1,     g_C1);
    cudaGetSymbolAddress((void**)&C2,     g_C2);
    cudaGetSymbolAddress((void**)&G1,     g_G1);
    cudaGetSymbolAddress((void**)&G2,     g_G2);
    cudaGetSymbolAddress((void**)&hbuf,   g_h);
    cudaGetSymbolAddress((void**)&x16,    g_x16);
    cudaGetSymbolAddress((void**)&h16,    g_h16);
    cudaGetSymbolAddress((void**)&Wrec16, g_Wrec16);
    cudaGetSymbolAddress((void**)&tauh16, g_tauh16);
    cudaGetSymbolAddress((void**)&Win16,  g_Win16);
    cudaGetSymbolAddress((void**)&taux16, g_taux16);

    cudaFuncSetAttribute(gemm_dual_f16, cudaFuncAttributeMaxDynamicSharedMemorySize, SMEM_TOTAL);

    const int ldtau = I_SZ + H_SZ;     // 3072

    // ---- one-time fp16 conversions ----
    const int CVB = 512;
    cvt16_kernel<<<CVB, 256>>>(x,                  I_SZ,  x16,    I_SZ,  B_SZ, I_SZ);
    cvt16_kernel<<<CVB, 256>>>(hidden,             H_SZ,  h16,    H_SZ,  B_SZ, H_SZ);
    cvt16_kernel<<<CVB, 256>>>(W_rec,              H_SZ,  Wrec16, H_SZ,  H_SZ, H_SZ);
    cvt16_kernel<<<CVB, 256>>>(tau_adapt_w + I_SZ, ldtau, tauh16, H_SZ,  H_SZ, H_SZ);
    cvt16_kernel<<<CVB, 256>>>(W_in_w,             I_SZ,  Win16,  I_SZ,  H_SZ, I_SZ);
    cvt16_kernel<<<CVB, 256>>>(tau_adapt_w,        ldtau, taux16, I_SZ,  H_SZ, I_SZ);

    dim3 gg(16, B_SZ / BM);            // (16, 32) = 512 CTAs

    // invariant GEMMs fused: C1 = x@W_in^T + b, C2 = x@tau_x^T + tb
    gemm_dual_f16<<<gg, THREADS, SMEM_TOTAL>>>(
        x16, I_SZ,
        Win16, I_SZ, C1, W_in_b,
        taux16, I_SZ, C2, tau_adapt_b,
        I_SZ);

    const float* h = hidden;
    const int n_ew = (B_SZ * H_SZ) / 4 / 256;
    for (int s = 0; s < NSTEPS; s++) {
        // in-loop GEMMs fused: G1 = h@tau_h^T, G2 = h@W_rec^T  (A = fp16 h)
        gemm_dual_f16<<<gg, THREADS, SMEM_TOTAL>>>(
            h16, H_SZ,
            tauh16, H_SZ, G1, nullptr,
            Wrec16, H_SZ, G2, nullptr,
            H_SZ);

        float* ho = (s == NSTEPS - 1) ? out_h   : hbuf;
        float* to = (s == NSTEPS - 1) ? out_tau : nullptr;
        liquid_step_kernel<<<n_ew, 256>>>(h, G1, G2, C1, C2, tau_base, ho, h16, to);
        h = ho;
    }
}

// round 12
// speedup vs baseline: 2.0694x; 1.0385x over previous
#include <cuda_runtime.h>
#include <cuda_fp16.h>
#include <cstdint>

// -------------------- problem constants --------------------
#define B_SZ 4096
#define I_SZ 1024
#define H_SZ 2048
#define NSTEPS 5
#define DT_C 0.1f

// -------------------- GEMM tiling (R4 structure, fp16 data) ---------------
#define BM 128
#define BN 256
#define BK 32                 // 32 halves per k-tile = 64B rows
#define NSTAGE 4
#define THREADS 256

#define SA_BYTES (BM * 64)                    // 8192
#define SB_BYTES (BN * 64)                    // 16384
#define STAGE_BYTES (SA_BYTES + SB_BYTES)     // 24576
#define SMEM_TOTAL (NSTAGE * STAGE_BYTES)     // 98304

// -------------------- scratch --------------------
__device__ __half g_C1h[B_SZ * H_SZ];
__device__ __half g_C2h[B_SZ * H_SZ];
__device__ __half g_G1h[B_SZ * H_SZ];
__device__ __half g_G2h[B_SZ * H_SZ];
__device__ float  g_h  [B_SZ * H_SZ];
__device__ __half g_h16  [B_SZ * H_SZ];
__device__ __half g_x16  [B_SZ * I_SZ];
__device__ __half g_Wrec16[H_SZ * H_SZ];
__device__ __half g_tauh16[H_SZ * H_SZ];
__device__ __half g_Win16 [H_SZ * I_SZ];
__device__ __half g_taux16[H_SZ * I_SZ];

// -------------------- PTX helpers --------------------
__device__ __forceinline__ void cp16(uint32_t smem, const void* g) {
    asm volatile("cp.async.cg.shared.global [%0], [%1], 16;" :: "r"(smem), "l"(g) : "memory");
}
__device__ __forceinline__ void cp_commit() {
    asm volatile("cp.async.commit_group;" ::: "memory");
}
template <int N>
__device__ __forceinline__ void cp_wait() {
    asm volatile("cp.async.wait_group %0;" :: "n"(N) : "memory");
}
__device__ __forceinline__ void ldsm4(uint32_t* r, uint32_t a) {
    asm volatile("ldmatrix.sync.aligned.m8n8.x4.shared.b16 {%0,%1,%2,%3}, [%4];"
                 : "=r"(r[0]), "=r"(r[1]), "=r"(r[2]), "=r"(r[3]) : "r"(a));
}
__device__ __forceinline__ void mma_f16(float* d, const uint32_t* a, const uint32_t* b) {
    asm volatile(
        "mma.sync.aligned.m16n8k16.row.col.f32.f16.f16.f32 "
        "{%0,%1,%2,%3}, {%4,%5,%6,%7}, {%8,%9}, {%0,%1,%2,%3};"
        : "+f"(d[0]), "+f"(d[1]), "+f"(d[2]), "+f"(d[3])
        : "r"(a[0]), "r"(a[1]), "r"(a[2]), "r"(a[3]), "r"(b[0]), "r"(b[1]));
}
__device__ __forceinline__ uint32_t swadr(uint32_t base, int r, int g) {
    const int c = g ^ (r & 3) ^ ((r >> 2) & 1);
    return base + (uint32_t)(r * 64 + c * 16);
}
__device__ __forceinline__ float4 h4_to_f4(uint2 u) {
    const __half2 a = *(__half2*)&u.x;
    const __half2 b = *(__half2*)&u.y;
    const float2 fa = __half22float2(a);
    const float2 fb = __half22float2(b);
    return make_float4(fa.x, fa.y, fb.x, fb.y);
}

// -------------------- fused fp32 -> fp16 convert (all jobs, one launch) ----
struct CvtJob { const float* s; __half* d; int rows, cols, sld, dld; };
struct CvtJobs { CvtJob j[6]; };

__global__ void cvt_all_kernel(CvtJobs J)
{
    const CvtJob job = J.j[blockIdx.y];
    const int per_row = job.cols >> 3;
    const long total = (long)job.rows * per_row;
    for (long i = (long)blockIdx.x * blockDim.x + threadIdx.x; i < total;
         i += (long)gridDim.x * blockDim.x) {
        const int r = (int)(i / per_row);
        const int c = (int)(i % per_row) << 3;
        const float4 a = *(const float4*)(job.s + (long)r * job.sld + c);
        const float4 b = *(const float4*)(job.s + (long)r * job.sld + c + 4);
        __half2 h0 = __float22half2_rn(make_float2(a.x, a.y));
        __half2 h1 = __float22half2_rn(make_float2(a.z, a.w));
        __half2 h2 = __float22half2_rn(make_float2(b.x, b.y));
        __half2 h3 = __float22half2_rn(make_float2(b.z, b.w));
        uint4 u;
        u.x = *(uint32_t*)&h0; u.y = *(uint32_t*)&h1;
        u.z = *(uint32_t*)&h2; u.w = *(uint32_t*)&h3;
        *(uint4*)(job.d + (long)r * job.dld + c) = u;
    }
}

// -------------------- dual-B fp16 GEMM (R4 body), fp16 output --------------
// C_half[M, H_SZ] (fp16): tile = A[m0:+128, :K] @ Bh[n0:+256, :K]^T (+bias_h)
__global__ void __launch_bounds__(THREADS, 1)
gemm_dual_f16(const __half* __restrict__ A, int lda,
              const __half* __restrict__ B0, int ldb0, __half* __restrict__ C0,
              const float* __restrict__ bias0,
              const __half* __restrict__ B1, int ldb1, __half* __restrict__ C1,
              const float* __restrict__ bias1,
              int K)
{
    extern __shared__ __align__(1024) char smem[];
    const uint32_t sb = (uint32_t)__cvta_generic_to_shared(smem);

    const int tid  = threadIdx.x;
    const int lane = tid & 31;
    const int wid  = tid >> 5;
    const int wm   = (wid >> 2) * 64;
    const int wn   = (wid & 3) * 64;

    const int half_ = blockIdx.x >> 3;
    const int nblk  = blockIdx.x & 7;
    const int m0 = blockIdx.y * BM;
    const int n0 = nblk * BN;

    const __half* Bw   = half_ ? B1 : B0;
    const int     ldb  = half_ ? ldb1 : ldb0;
    __half*       C    = half_ ? C1 : C0;
    const float*  bias = half_ ? bias1 : bias0;

    const int lr = tid >> 2;
    const int lg = tid & 3;
    const __half* gA = A  + (long)(m0 + lr) * lda + lg * 8;
    const __half* gB = Bw + (long)(n0 + lr) * ldb + lg * 8;
    const long strideA64 = (long)64 * lda;
    const long strideB64 = (long)64 * ldb;

    const int arow = (lane & 7) + ((lane >> 3) & 1) * 8;
    const int agof = (lane >> 4);
    const int brow = (lane & 7) + ((lane >> 4) & 1) * 8;
    const int bgof = (lane >> 3) & 1;

    float acc[4][8][4];
#pragma unroll
    for (int mt = 0; mt < 4; mt++)
#pragma unroll
        for (int nt = 0; nt < 8; nt++)
#pragma unroll
            for (int r = 0; r < 4; r++) acc[mt][nt][r] = 0.f;

    const int nK = K / BK;

    auto load_stage = [&](int s, int kt) {
        const uint32_t sA = sb + s * STAGE_BYTES;
        const uint32_t sB = sA + SA_BYTES;
        const int koff = kt * BK;
        cp16(swadr(sA, lr,       lg), gA + koff);
        cp16(swadr(sA, lr + 64,  lg), gA + koff + strideA64);
        cp16(swadr(sB, lr,       lg), gB + koff);
        cp16(swadr(sB, lr + 64,  lg), gB + koff + strideB64);
        cp16(swadr(sB, lr + 128, lg), gB + koff + 2 * strideB64);
        cp16(swadr(sB, lr + 192, lg), gB + koff + 3 * strideB64);
    };

#pragma unroll
    for (int s = 0; s < NSTAGE - 1; s++) {
        load_stage(s, s);
        cp_commit();
    }

    for (int kt = 0; kt < nK; kt++) {
        cp_wait<NSTAGE - 2>();
        __syncthreads();

        const int kload = kt + NSTAGE - 1;
        if (kload < nK) load_stage(kload & (NSTAGE - 1), kload);
        cp_commit();

        const uint32_t sA = sb + (kt & (NSTAGE - 1)) * STAGE_BYTES;
        const uint32_t sB = sA + SA_BYTES;

#pragma unroll
        for (int ks = 0; ks < 2; ks++) {
            uint32_t af[4][4], bf[4][4];
#pragma unroll
            for (int mt = 0; mt < 4; mt++)
                ldsm4(af[mt], swadr(sA, wm + mt * 16 + arow, 2 * ks + agof));
#pragma unroll
            for (int p = 0; p < 4; p++)
                ldsm4(bf[p], swadr(sB, wn + p * 16 + brow, 2 * ks + bgof));
#pragma unroll
            for (int mt = 0; mt < 4; mt++)
#pragma unroll
                for (int p = 0; p < 4; p++) {
                    mma_f16(acc[mt][2 * p],     af[mt], &bf[p][0]);
                    mma_f16(acc[mt][2 * p + 1], af[mt], &bf[p][2]);
                }
        }
    }

    // ---- epilogue: fp16 stores ----
    const int grp = lane >> 2;
    const int tig = lane & 3;
#pragma unroll
    for (int mt = 0; mt < 4; mt++) {
        const int row0 = m0 + wm + mt * 16 + grp;
#pragma unroll
        for (int nt = 0; nt < 8; nt++) {
            const int col = n0 + wn + nt * 8 + 2 * tig;
            float b0 = 0.f, b1 = 0.f;
            if (bias) { b0 = __ldg(bias + col); b1 = __ldg(bias + col + 1); }
            __half2 p0 = __floats2half2_rn(acc[mt][nt][0] + b0, acc[mt][nt][1] + b1);
            __half2 p1 = __floats2half2_rn(acc[mt][nt][2] + b0, acc[mt][nt][3] + b1);
            *(__half2*)(C + (long)row0 * H_SZ + col)       = p0;
            *(__half2*)(C + (long)(row0 + 8) * H_SZ + col) = p1;
        }
    }
}

// -------------------- elementwise liquid step (fp16 inputs) ----------------
__global__ void __launch_bounds__(256)
liquid_step_kernel(const float* __restrict__ h_in,
                   const __half* __restrict__ G1,
                   const __half* __restrict__ G2,
                   const __half* __restrict__ C1,
                   const __half* __restrict__ C2,
                   const float* __restrict__ tau_base,
                   float* __restrict__ h_out,
                   __half* __restrict__ h16_out,
                   float* __restrict__ tau_out)
{
    const int idx = (blockIdx.x * 256 + threadIdx.x) * 4;
    const int j = idx & (H_SZ - 1);

    float4 g1 = h4_to_f4(*(const uint2*)(G1 + idx));
    float4 g2 = h4_to_f4(*(const uint2*)(G2 + idx));
    float4 c1 = h4_to_f4(*(const uint2*)(C1 + idx));
    float4 c2 = h4_to_f4(*(const uint2*)(C2 + idx));
    float4 hv = *(const float4*)(h_in + idx);
    float4 tb = *(const float4*)(tau_base + j);

    float4 hn, tv;
#define ONE_LANE(f)                                                        \
    {                                                                      \
        float tl  = c2.f + g1.f;                                           \
        float sg  = 1.f / (1.f + expf(-tl));                               \
        float tau = tb.f * (0.5f + sg);                                    \
        float act = tanhf(g2.f + c1.f);                                    \
        hn.f = hv.f + DT_C * (act - hv.f) / tau;                           \
        tv.f = tau;                                                        \
    }
    ONE_LANE(x) ONE_LANE(y) ONE_LANE(z) ONE_LANE(w)
#undef ONE_LANE

    *(float4*)(h_out + idx) = hn;
    __half2 p0 = __float22half2_rn(make_float2(hn.x, hn.y));
    __half2 p1 = __float22half2_rn(make_float2(hn.z, hn.w));
    uint2 u; u.x = *(uint32_t*)&p0; u.y = *(uint32_t*)&p1;
    *(uint2*)(h16_out + idx) = u;
    if (tau_out) *(float4*)(tau_out + idx) = tv;
}

// -------------------- launcher --------------------
extern "C" void kernel_launch(void* const* d_in, const int* in_sizes, int n_in,
                              void* d_out, int out_size)
{
    (void)in_sizes; (void)n_in; (void)out_size;

    const float* x           = (const float*)d_in[0];
    const float* hidden      = (const float*)d_in[1];
    const float* W_rec       = (const float*)d_in[2];
    const float* W_in_w      = (const float*)d_in[3];
    const float* W_in_b      = (const float*)d_in[4];
    const float* tau_base    = (const float*)d_in[5];
    const float* tau_adapt_w = (const float*)d_in[6];
    const float* tau_adapt_b = (const float*)d_in[7];

    float* out_h   = (float*)d_out;
    float* out_tau = out_h + (long)B_SZ * H_SZ;

    __half *C1h, *C2h, *G1h, *G2h, *x16, *h16, *Wrec16, *tauh16, *Win16, *taux16;
    float* hbuf;
    cudaGetSymbolAddress((void**)&C1h,    g_C1h);
    cudaGetSymbolAddress((void**)&C2h,    g_C2h);
    cudaGetSymbolAddress((void**)&G1h,    g_G1h);
    cudaGetSymbolAddress((void**)&G2h,    g_G2h);
    cudaGetSymbolAddress((void**)&hbuf,   g_h);
    cudaGetSymbolAddress((void**)&x16,    g_x16);
    cudaGetSymbolAddress((void**)&h16,    g_h16);
    cudaGetSymbolAddress((void**)&Wrec16, g_Wrec16);
    cudaGetSymbolAddress((void**)&tauh16, g_tauh16);
    cudaGetSymbolAddress((void**)&Win16,  g_Win16);
    cudaGetSymbolAddress((void**)&taux16, g_taux16);

    cudaFuncSetAttribute(gemm_dual_f16, cudaFuncAttributeMaxDynamicSharedMemorySize, SMEM_TOTAL);

    const int ldtau = I_SZ + H_SZ;     // 3072

    // ---- one fused conversion launch ----
    CvtJobs J;
    J.j[0] = {x,                  x16,    B_SZ, I_SZ, I_SZ,  I_SZ};
    J.j[1] = {hidden,             h16,    B_SZ, H_SZ, H_SZ,  H_SZ};
    J.j[2] = {W_rec,              Wrec16, H_SZ, H_SZ, H_SZ,  H_SZ};
    J.j[3] = {tau_adapt_w + I_SZ, tauh16, H_SZ, H_SZ, ldtau, H_SZ};
    J.j[4] = {W_in_w,             Win16,  H_SZ, I_SZ, I_SZ,  I_SZ};
    J.j[5] = {tau_adapt_w,        taux16, H_SZ, I_SZ, ldtau, I_SZ};
    cvt_all_kernel<<<dim3(128, 6), 256>>>(J);

    dim3 gg(16, B_SZ / BM);            // (16, 32) = 512 CTAs

    // invariant GEMMs fused: C1 = x@W_in^T + b, C2 = x@tau_x^T + tb  (fp16 out)
    gemm_dual_f16<<<gg, THREADS, SMEM_TOTAL>>>(
        x16, I_SZ,
        Win16, I_SZ, C1h, W_in_b,
        taux16, I_SZ, C2h, tau_adapt_b,
        I_SZ);

    const float* h = hidden;
    const int n_ew = (B_SZ * H_SZ) / 4 / 256;
    for (int s = 0; s < NSTEPS; s++) {
        // in-loop GEMMs fused: G1 = h@tau_h^T, G2 = h@W_rec^T  (fp16 in/out)
        gemm_dual_f16<<<gg, THREADS, SMEM_TOTAL>>>(
            h16, H_SZ,
            tauh16, H_SZ, G1h, nullptr,
            Wrec16, H_SZ, G2h, nullptr,
            H_SZ);

        float* ho = (s == NSTEPS - 1) ? out_h   : hbuf;
        float* to = (s == NSTEPS - 1) ? out_tau : nullptr;
        liquid_step_kernel<<<n_ew, 256>>>(h, G1h, G2h, C1h, C2h, tau_base, ho, h16, to);
        h = ho;
    }
}

// round 13
// speedup vs baseline: 2.1689x; 1.0481x over previous
#include <cuda_runtime.h>
#include <cuda_fp16.h>
#include <cstdint>

// -------------------- problem constants --------------------
#define B_SZ 4096
#define I_SZ 1024
#define H_SZ 2048
#define NSTEPS 5
#define DT_C 0.1f

// -------------------- GEMM tiling (R4 structure, fp16 data) ---------------
#define BM 128
#define BN 256
#define BK 32                 // 32 halves per k-tile = 64B rows
#define NSTAGE 4
#define THREADS 256

#define SA_BYTES (BM * 64)                    // 8192
#define SB_BYTES (BN * 64)                    // 16384
#define STAGE_BYTES (SA_BYTES + SB_BYTES)     // 24576
#define SMEM_TOTAL (NSTAGE * STAGE_BYTES)     // 98304

// -------------------- scratch --------------------
__device__ __half g_C1h[B_SZ * H_SZ];
__device__ __half g_C2h[B_SZ * H_SZ];
__device__ __half g_G1h[B_SZ * H_SZ];
__device__ __half g_G2h[B_SZ * H_SZ];
__device__ __half g_h16  [B_SZ * H_SZ];
__device__ __half g_x16  [B_SZ * I_SZ];
__device__ __half g_Wrec16[H_SZ * H_SZ];
__device__ __half g_tauh16[H_SZ * H_SZ];
__device__ __half g_Win16 [H_SZ * I_SZ];
__device__ __half g_taux16[H_SZ * I_SZ];

// -------------------- PTX helpers --------------------
__device__ __forceinline__ void cp16(uint32_t smem, const void* g) {
    asm volatile("cp.async.cg.shared.global [%0], [%1], 16;" :: "r"(smem), "l"(g) : "memory");
}
__device__ __forceinline__ void cp_commit() {
    asm volatile("cp.async.commit_group;" ::: "memory");
}
template <int N>
__device__ __forceinline__ void cp_wait() {
    asm volatile("cp.async.wait_group %0;" :: "n"(N) : "memory");
}
__device__ __forceinline__ void ldsm4(uint32_t* r, uint32_t a) {
    asm volatile("ldmatrix.sync.aligned.m8n8.x4.shared.b16 {%0,%1,%2,%3}, [%4];"
                 : "=r"(r[0]), "=r"(r[1]), "=r"(r[2]), "=r"(r[3]) : "r"(a));
}
__device__ __forceinline__ void mma_f16(float* d, const uint32_t* a, const uint32_t* b) {
    asm volatile(
        "mma.sync.aligned.m16n8k16.row.col.f32.f16.f16.f32 "
        "{%0,%1,%2,%3}, {%4,%5,%6,%7}, {%8,%9}, {%0,%1,%2,%3};"
        : "+f"(d[0]), "+f"(d[1]), "+f"(d[2]), "+f"(d[3])
        : "r"(a[0]), "r"(a[1]), "r"(a[2]), "r"(a[3]), "r"(b[0]), "r"(b[1]));
}
__device__ __forceinline__ uint32_t swadr(uint32_t base, int r, int g) {
    const int c = g ^ (r & 3) ^ ((r >> 2) & 1);
    return base + (uint32_t)(r * 64 + c * 16);
}
__device__ __forceinline__ float4 h4_to_f4(uint2 u) {
    const __half2 a = *(__half2*)&u.x;
    const __half2 b = *(__half2*)&u.y;
    const float2 fa = __half22float2(a);
    const float2 fb = __half22float2(b);
    return make_float4(fa.x, fa.y, fb.x, fb.y);
}

// -------------------- fused fp32 -> fp16 convert (all jobs, one launch) ----
struct CvtJob { const float* s; __half* d; int rows, cols, sld, dld; };
struct CvtJobs { CvtJob j[6]; };

__global__ void cvt_all_kernel(CvtJobs J)
{
    const CvtJob job = J.j[blockIdx.y];
    const int per_row = job.cols >> 3;
    const long total = (long)job.rows * per_row;
    for (long i = (long)blockIdx.x * blockDim.x + threadIdx.x; i < total;
         i += (long)gridDim.x * blockDim.x) {
        const int r = (int)(i / per_row);
        const int c = (int)(i % per_row) << 3;
        const float4 a = *(const float4*)(job.s + (long)r * job.sld + c);
        const float4 b = *(const float4*)(job.s + (long)r * job.sld + c + 4);
        __half2 h0 = __float22half2_rn(make_float2(a.x, a.y));
        __half2 h1 = __float22half2_rn(make_float2(a.z, a.w));
        __half2 h2 = __float22half2_rn(make_float2(b.x, b.y));
        __half2 h3 = __float22half2_rn(make_float2(b.z, b.w));
        uint4 u;
        u.x = *(uint32_t*)&h0; u.y = *(uint32_t*)&h1;
        u.z = *(uint32_t*)&h2; u.w = *(uint32_t*)&h3;
        *(uint4*)(job.d + (long)r * job.dld + c) = u;
    }
}

// -------------------- dual-B fp16 GEMM (R4 body), job-table ----------------
// Each job: two GEMMs (B0->C0, B1->C1) over the full [M, H_SZ] output.
// grid.x = 16 (one job) or 32 (two jobs, job = blockIdx.x >> 4).
struct GemmJob {
    const __half *A; int lda;
    const __half *B0; int ldb0; __half *C0; const float *bias0;
    const __half *B1; int ldb1; __half *C1; const float *bias1;
    int K;
};

__global__ void __launch_bounds__(THREADS, 1)
gemm_dual_f16(GemmJob j0, GemmJob j1)
{
    extern __shared__ __align__(1024) char smem[];
    const uint32_t sb = (uint32_t)__cvta_generic_to_shared(smem);

    const int tid  = threadIdx.x;
    const int lane = tid & 31;
    const int wid  = tid >> 5;
    const int wm   = (wid >> 2) * 64;
    const int wn   = (wid & 3) * 64;

    const GemmJob jb = (blockIdx.x >> 4) ? j1 : j0;
    const int half_ = (blockIdx.x >> 3) & 1;
    const int nblk  = blockIdx.x & 7;
    const int m0 = blockIdx.y * BM;
    const int n0 = nblk * BN;

    const __half* A    = jb.A;
    const int     lda  = jb.lda;
    const __half* Bw   = half_ ? jb.B1 : jb.B0;
    const int     ldb  = half_ ? jb.ldb1 : jb.ldb0;
    __half*       C    = half_ ? jb.C1 : jb.C0;
    const float*  bias = half_ ? jb.bias1 : jb.bias0;
    const int     K    = jb.K;

    const int lr = tid >> 2;
    const int lg = tid & 3;
    const __half* gA = A  + (long)(m0 + lr) * lda + lg * 8;
    const __half* gB = Bw + (long)(n0 + lr) * ldb + lg * 8;
    const long strideA64 = (long)64 * lda;
    const long strideB64 = (long)64 * ldb;

    const int arow = (lane & 7) + ((lane >> 3) & 1) * 8;
    const int agof = (lane >> 4);
    const int brow = (lane & 7) + ((lane >> 4) & 1) * 8;
    const int bgof = (lane >> 3) & 1;

    float acc[4][8][4];
#pragma unroll
    for (int mt = 0; mt < 4; mt++)
#pragma unroll
        for (int nt = 0; nt < 8; nt++)
#pragma unroll
            for (int r = 0; r < 4; r++) acc[mt][nt][r] = 0.f;

    const int nK = K / BK;

    auto load_stage = [&](int s, int kt) {
        const uint32_t sA = sb + s * STAGE_BYTES;
        const uint32_t sB = sA + SA_BYTES;
        const int koff = kt * BK;
        cp16(swadr(sA, lr,       lg), gA + koff);
        cp16(swadr(sA, lr + 64,  lg), gA + koff + strideA64);
        cp16(swadr(sB, lr,       lg), gB + koff);
        cp16(swadr(sB, lr + 64,  lg), gB + koff + strideB64);
        cp16(swadr(sB, lr + 128, lg), gB + koff + 2 * strideB64);
        cp16(swadr(sB, lr + 192, lg), gB + koff + 3 * strideB64);
    };

#pragma unroll
    for (int s = 0; s < NSTAGE - 1; s++) {
        load_stage(s, s);
        cp_commit();
    }

    for (int kt = 0; kt < nK; kt++) {
        cp_wait<NSTAGE - 2>();
        __syncthreads();

        const int kload = kt + NSTAGE - 1;
        if (kload < nK) load_stage(kload & (NSTAGE - 1), kload);
        cp_commit();

        const uint32_t sA = sb + (kt & (NSTAGE - 1)) * STAGE_BYTES;
        const uint32_t sB = sA + SA_BYTES;

#pragma unroll
        for (int ks = 0; ks < 2; ks++) {
            uint32_t af[4][4], bf[4][4];
#pragma unroll
            for (int mt = 0; mt < 4; mt++)
                ldsm4(af[mt], swadr(sA, wm + mt * 16 + arow, 2 * ks + agof));
#pragma unroll
            for (int p = 0; p < 4; p++)
                ldsm4(bf[p], swadr(sB, wn + p * 16 + brow, 2 * ks + bgof));
#pragma unroll
            for (int mt = 0; mt < 4; mt++)
#pragma unroll
                for (int p = 0; p < 4; p++) {
                    mma_f16(acc[mt][2 * p],     af[mt], &bf[p][0]);
                    mma_f16(acc[mt][2 * p + 1], af[mt], &bf[p][2]);
                }
        }
    }

    // ---- epilogue: fp16 stores ----
    const int grp = lane >> 2;
    const int tig = lane & 3;
#pragma unroll
    for (int mt = 0; mt < 4; mt++) {
        const int row0 = m0 + wm + mt * 16 + grp;
#pragma unroll
        for (int nt = 0; nt < 8; nt++) {
            const int col = n0 + wn + nt * 8 + 2 * tig;
            float b0 = 0.f, b1 = 0.f;
            if (bias) { b0 = __ldg(bias + col); b1 = __ldg(bias + col + 1); }
            __half2 p0 = __floats2half2_rn(acc[mt][nt][0] + b0, acc[mt][nt][1] + b1);
            __half2 p1 = __floats2half2_rn(acc[mt][nt][2] + b0, acc[mt][nt][3] + b1);
            *(__half2*)(C + (long)row0 * H_SZ + col)       = p0;
            *(__half2*)(C + (long)(row0 + 8) * H_SZ + col) = p1;
        }
    }
}

// -------------------- elementwise liquid step (fp16 state, in place) -------
__global__ void __launch_bounds__(256)
liquid_step_kernel(__half* __restrict__ h16,         // read + write (in place)
                   const __half* __restrict__ G1,
                   const __half* __restrict__ G2,
                   const __half* __restrict__ C1,
                   const __half* __restrict__ C2,
                   const float* __restrict__ tau_base,
                   float* __restrict__ h_out,        // fp32, last step only
                   float* __restrict__ tau_out)      // fp32, last step only
{
    const int idx = (blockIdx.x * 256 + threadIdx.x) * 4;
    const int j = idx & (H_SZ - 1);

    float4 g1 = h4_to_f4(*(const uint2*)(G1 + idx));
    float4 g2 = h4_to_f4(*(const uint2*)(G2 + idx));
    float4 c1 = h4_to_f4(*(const uint2*)(C1 + idx));
    float4 c2 = h4_to_f4(*(const uint2*)(C2 + idx));
    float4 hv = h4_to_f4(*(const uint2*)(h16 + idx));
    float4 tb = *(const float4*)(tau_base + j);

    float4 hn, tv;
#define ONE_LANE(f)                                                        \
    {                                                                      \
        float tl  = c2.f + g1.f;                                           \
        float sg  = 1.f / (1.f + expf(-tl));                               \
        float tau = tb.f * (0.5f + sg);                                    \
        float act = tanhf(g2.f + c1.f);                                    \
        hn.f = hv.f + DT_C * (act - hv.f) / tau;                           \
        tv.f = tau;                                                        \
    }
    ONE_LANE(x) ONE_LANE(y) ONE_LANE(z) ONE_LANE(w)
#undef ONE_LANE

    __half2 p0 = __float22half2_rn(make_float2(hn.x, hn.y));
    __half2 p1 = __float22half2_rn(make_float2(hn.z, hn.w));
    uint2 u; u.x = *(uint32_t*)&p0; u.y = *(uint32_t*)&p1;
    *(uint2*)(h16 + idx) = u;

    if (h_out)   *(float4*)(h_out + idx)   = hn;
    if (tau_out) *(float4*)(tau_out + idx) = tv;
}

// -------------------- launcher --------------------
extern "C" void kernel_launch(void* const* d_in, const int* in_sizes, int n_in,
                              void* d_out, int out_size)
{
    (void)in_sizes; (void)n_in; (void)out_size;

    const float* x           = (const float*)d_in[0];
    const float* hidden      = (const float*)d_in[1];
    const float* W_rec       = (const float*)d_in[2];
    const float* W_in_w      = (const float*)d_in[3];
    const float* W_in_b      = (const float*)d_in[4];
    const float* tau_base    = (const float*)d_in[5];
    const float* tau_adapt_w = (const float*)d_in[6];
    const float* tau_adapt_b = (const float*)d_in[7];

    float* out_h   = (float*)d_out;
    float* out_tau = out_h + (long)B_SZ * H_SZ;

    __half *C1h, *C2h, *G1h, *G2h, *x16, *h16, *Wrec16, *tauh16, *Win16, *taux16;
    cudaGetSymbolAddress((void**)&C1h,    g_C1h);
    cudaGetSymbolAddress((void**)&C2h,    g_C2h);
    cudaGetSymbolAddress((void**)&G1h,    g_G1h);
    cudaGetSymbolAddress((void**)&G2h,    g_G2h);
    cudaGetSymbolAddress((void**)&x16,    g_x16);
    cudaGetSymbolAddress((void**)&h16,    g_h16);
    cudaGetSymbolAddress((void**)&Wrec16, g_Wrec16);
    cudaGetSymbolAddress((void**)&tauh16, g_tauh16);
    cudaGetSymbolAddress((void**)&Win16,  g_Win16);
    cudaGetSymbolAddress((void**)&taux16, g_taux16);

    cudaFuncSetAttribute(gemm_dual_f16, cudaFuncAttributeMaxDynamicSharedMemorySize, SMEM_TOTAL);

    const int ldtau = I_SZ + H_SZ;     // 3072

    // ---- one fused conversion launch ----
    CvtJobs J;
    J.j[0] = {x,                  x16,    B_SZ, I_SZ, I_SZ,  I_SZ};
    J.j[1] = {hidden,             h16,    B_SZ, H_SZ, H_SZ,  H_SZ};
    J.j[2] = {W_rec,              Wrec16, H_SZ, H_SZ, H_SZ,  H_SZ};
    J.j[3] = {tau_adapt_w + I_SZ, tauh16, H_SZ, H_SZ, ldtau, H_SZ};
    J.j[4] = {W_in_w,             Win16,  I_SZ, H_SZ, I_SZ,  I_SZ};
    J.j[5] = {tau_adapt_w,        taux16, H_SZ, I_SZ, ldtau, I_SZ};
    // (rows/cols for j[4] corrected: W_in_w is [H_SZ, I_SZ])
    J.j[4] = {W_in_w,             Win16,  H_SZ, I_SZ, I_SZ,  I_SZ};
    cvt_all_kernel<<<dim3(128, 6), 256>>>(J);

    // ---- merged launch: invariant GEMMs (job0) + step-0 GEMMs (job1) ----
    GemmJob inv  = { x16, I_SZ,
                     Win16,  I_SZ, C1h, W_in_b,
                     taux16, I_SZ, C2h, tau_adapt_b,
                     I_SZ };
    GemmJob loop = { h16, H_SZ,
                     tauh16, H_SZ, G1h, nullptr,
                     Wrec16, H_SZ, G2h, nullptr,
                     H_SZ };

    gemm_dual_f16<<<dim3(32, B_SZ / BM), THREADS, SMEM_TOTAL>>>(inv, loop);

    const int n_ew = (B_SZ * H_SZ) / 4 / 256;
    for (int s = 0; s < NSTEPS; s++) {
        if (s > 0)
            gemm_dual_f16<<<dim3(16, B_SZ / BM), THREADS, SMEM_TOTAL>>>(loop, loop);

        float* ho = (s == NSTEPS - 1) ? out_h   : nullptr;
        float* to = (s == NSTEPS - 1) ? out_tau : nullptr;
        liquid_step_kernel<<<n_ew, 256>>>(h16, G1h, G2h, C1h, C2h, tau_base, ho, to);
    }
}